// round 2
// baseline (speedup 1.0000x reference)
#include <cuda_runtime.h>

#define NL 200
#define NH 64
#define SUMS_SZ (NL * NH)

// Scratch (allocation-free): per-dataset segment sums and counts.
// g_sums column layout is PERMUTED: col c stored at slot (c>>1) + 32*(c&1).
__device__ float g_sums[2][SUMS_SZ];
__device__ float g_cnts[2][NL];

__global__ void zero_kernel() {
    int i = blockIdx.x * blockDim.x + threadIdx.x;
    if (i < SUMS_SZ) { g_sums[0][i] = 0.f; g_sums[1][i] = 0.f; }
    if (i < NL)      { g_cnts[0][i] = 0.f; g_cnts[1][i] = 0.f; }
}

// grid (NBLK, 2): y = dataset. Warp-per-row; lane k carries cols (2k, 2k+1)
// via one LDG.64, accumulated into permuted smem slots k and k+32 (bank k,
// conflict-free). Labels loaded once per 32-row chunk and shfl-broadcast.
__global__ __launch_bounds__(512, 4)
void accum_kernel(const float2* __restrict__ lat0, const int* __restrict__ lab0,
                  const float2* __restrict__ lat1, const int* __restrict__ lab1,
                  int n_rows)
{
    extern __shared__ float smem[];
    float* s_sums = smem;            // SUMS_SZ floats (permuted cols)
    float* s_cnt  = smem + SUMS_SZ;  // NL floats

    const int ds = blockIdx.y;
    const float2* __restrict__ lat = ds ? lat1 : lat0;
    const int*    __restrict__ lab = ds ? lab1 : lab0;

    for (int i = threadIdx.x; i < SUMS_SZ; i += blockDim.x) s_sums[i] = 0.f;
    for (int i = threadIdx.x; i < NL; i += blockDim.x) s_cnt[i] = 0.f;
    __syncthreads();

    const int lane = threadIdx.x & 31;
    const int gw   = blockIdx.x * (blockDim.x >> 5) + (threadIdx.x >> 5);
    const int nwarps = gridDim.x * (blockDim.x >> 5);
    const int nchunks = n_rows >> 5;   // 32-row chunks

    for (int c = gw; c < nchunks; c += nwarps) {
        const int base = c << 5;
        const int labv = __ldg(lab + base + lane);     // 1 LDG / 32 rows
        atomicAdd(s_cnt + labv, 1.f);                  // 1 ATOMS / 32 rows
        const float2* __restrict__ p = lat + (size_t)base * 32 + lane;
        #pragma unroll 8
        for (int i = 0; i < 32; i++) {
            int l = __shfl_sync(0xffffffffu, labv, i);
            float2 v = __ldg(p + i * 32);
            float* dst = s_sums + l * NH + lane;
            atomicAdd(dst, v.x);        // slot lane   <- col 2*lane
            atomicAdd(dst + 32, v.y);   // slot lane+32<- col 2*lane+1
        }
    }

    // Tail rows (n_rows % 32): one warp handles them.
    if (gw == 0) {
        for (int r = nchunks << 5; r < n_rows; r++) {
            int l = __ldg(lab + r);
            float2 v = __ldg(lat + (size_t)r * 32 + lane);
            float* dst = s_sums + l * NH + lane;
            atomicAdd(dst, v.x);
            atomicAdd(dst + 32, v.y);
            if (lane == 0) atomicAdd(s_cnt + l, 1.f);
        }
    }
    __syncthreads();

    // Flush with vector atomics (sm_90+ float4 atomicAdd). Raw copy keeps the
    // permuted layout in g_sums; finalize un-permutes.
    float4* gs = reinterpret_cast<float4*>(g_sums[ds]);
    const float4* ss = reinterpret_cast<const float4*>(s_sums);
    for (int i = threadIdx.x; i < SUMS_SZ / 4; i += blockDim.x)
        atomicAdd(gs + i, ss[i]);
    for (int i = threadIdx.x; i < NL; i += blockDim.x)
        atomicAdd(&g_cnts[ds][i], s_cnt[i]);
}

// Single block: reset check, centroid update, MSE + KL -> scalar.
__global__ void finalize_kernel(const float* __restrict__ cent_p,
                                const float* __restrict__ pcnt,
                                const float* __restrict__ cent_t,
                                const float* __restrict__ tcnt,
                                const float* __restrict__ ncells,
                                float* __restrict__ out)
{
    __shared__ float red[256];
    __shared__ float s_n[2][NL];    // segment counts n
    __shared__ float s_c[2][NL];    // old counts (post-reset for pseudo)
    __shared__ float s_new[2][NL];  // updated counts
    int t = threadIdx.x;

    // reset pseudo_count if max >= NCELLS_MAX (= 200 * 1000)
    red[t] = (t < NL) ? pcnt[t] : -1e30f;
    __syncthreads();
    for (int s = 128; s > 0; s >>= 1) { if (t < s) red[t] = fmaxf(red[t], red[t + s]); __syncthreads(); }
    bool reset = (red[0] >= 200000.0f);
    __syncthreads();

    if (t < NL) {
        float n0 = g_cnts[0][t];
        float c0 = reset ? 1.0f : pcnt[t];
        s_n[0][t] = n0; s_c[0][t] = c0;
        s_new[0][t] = (n0 > 5.0f) ? (c0 + n0) : c0;
        float n1 = g_cnts[1][t];
        float c1 = tcnt[t];
        s_n[1][t] = n1; s_c[1][t] = c1;
        s_new[1][t] = (n1 > 5.0f) ? (c1 + n1) : c1;
    }
    __syncthreads();

    // MSE over updated centroids. centroids layout [H, L]: i = h*200 + l.
    // g_sums permuted layout: (label l, col h) at l*64 + (h>>1) + 32*(h&1).
    float acc = 0.f;
    for (int i = t; i < SUMS_SZ; i += 256) {
        int h = i / NL, l = i - h * NL;
        int slot = (h >> 1) + 32 * (h & 1);
        float cp = cent_p[i];
        float n0 = s_n[0][l];
        if (n0 > 5.0f) { float c0 = s_c[0][l]; cp = (cp * c0 + g_sums[0][l * NH + slot]) / (c0 + n0); }
        float ct = cent_t[i];
        float n1 = s_n[1][l];
        if (n1 > 5.0f) { float c1 = s_c[1][l]; ct = (ct * c1 + g_sums[1][l * NH + slot]) / (c1 + n1); }
        float d = cp - ct;
        acc += d * d;
    }

    // S = sum of updated pseudo counts
    red[t] = (t < NL) ? s_new[0][t] : 0.f;
    __syncthreads();
    for (int s = 128; s > 0; s >>= 1) { if (t < s) red[t] += red[t + s]; __syncthreads(); }
    float S = red[0];
    __syncthreads();

    float kl = 0.f;
    if (t < NL) {
        float p = s_new[0][t] / S;
        kl = p * (logf(p) - logf(ncells[t]));
    }

    red[t] = acc;
    __syncthreads();
    for (int s = 128; s > 0; s >>= 1) { if (t < s) red[t] += red[t + s]; __syncthreads(); }
    float mse_sum = red[0];
    __syncthreads();
    red[t] = kl;
    __syncthreads();
    for (int s = 128; s > 0; s >>= 1) { if (t < s) red[t] += red[t + s]; __syncthreads(); }
    if (t == 0) out[0] = mse_sum / (float)SUMS_SZ + red[0] / (float)NL;
}

extern "C" void kernel_launch(void* const* d_in, const int* in_sizes, int n_in,
                              void* d_out, int out_size)
{
    const float* p_lat  = (const float*)d_in[0];
    const int*   p_lab  = (const int*)  d_in[1];
    const float* t_lat  = (const float*)d_in[2];
    const int*   t_lab  = (const int*)  d_in[3];
    const float* cent_p = (const float*)d_in[4];
    const float* p_cnt  = (const float*)d_in[5];
    const float* cent_t = (const float*)d_in[6];
    const float* t_cnt  = (const float*)d_in[7];
    const float* ncells = (const float*)d_in[8];
    int n_rows = in_sizes[1];  // 1,000,000

    const int smem_bytes = (SUMS_SZ + NL) * (int)sizeof(float);
    cudaFuncSetAttribute(accum_kernel, cudaFuncAttributeMaxDynamicSharedMemorySize, smem_bytes);

    zero_kernel<<<(SUMS_SZ + 255) / 256, 256>>>();

    const int nblk = 296;  // 2 CTAs/SM per dataset -> 4 resident CTAs/SM total
    dim3 grid(nblk, 2);
    accum_kernel<<<grid, 512, smem_bytes>>>((const float2*)p_lat, p_lab,
                                            (const float2*)t_lat, t_lab, n_rows);

    finalize_kernel<<<1, 256>>>(cent_p, p_cnt, cent_t, t_cnt, ncells, (float*)d_out);
}

// round 3
// speedup vs baseline: 1.1591x; 1.1591x over previous
#include <cuda_runtime.h>

#define NL 200
#define NH 64
#define SUMS_SZ (NL * NH)
#define CHUNK 2048
#define QCAP 256          // per-queue capacity per chunk (mean 133, +11 sigma safe)
#define NWARP 16

// Scratch (allocation-free): per-dataset segment sums (standard [l*NH+h] layout) and counts.
__device__ float g_sums[2][SUMS_SZ];
__device__ float g_cnts[2][NL];

__global__ void zero_kernel() {
    int i = blockIdx.x * blockDim.x + threadIdx.x;
    if (i < SUMS_SZ) { g_sums[0][i] = 0.f; g_sums[1][i] = 0.f; }
    if (i < NL)      { g_cnts[0][i] = 0.f; g_cnts[1][i] = 0.f; }
}

// grid (148, 2): y = dataset. Warp w owns labels {w + 16j}. Rows are binned by
// label%16 into per-warp queues; each warp drains its queue accumulating into a
// PRIVATE smem table (plain LDS/STS RMW, no atomics on the data path).
__global__ __launch_bounds__(512, 2)
void accum_kernel(const float2* __restrict__ lat0, const int* __restrict__ lab0,
                  const float2* __restrict__ lat1, const int* __restrict__ lab1,
                  int n_rows, int rows_per_block)
{
    extern __shared__ char smem_raw[];
    // tables: float2[16 warps][13 labels][32 lanes] = 53248 B
    float2*   s_tab  = reinterpret_cast<float2*>(smem_raw);
    unsigned short* s_q = reinterpret_cast<unsigned short*>(smem_raw + 53248); // [16][QCAP] = 8192 B
    float*    s_cnt  = reinterpret_cast<float*>(smem_raw + 53248 + 8192);      // [200]
    int*      s_qtl  = reinterpret_cast<int*>(smem_raw + 53248 + 8192 + 800);  // [16]

    const int ds = blockIdx.y;
    const float2* __restrict__ lat = ds ? lat1 : lat0;
    const int*    __restrict__ lab = ds ? lab1 : lab0;

    const int tid  = threadIdx.x;
    const int lane = tid & 31;
    const int wid  = tid >> 5;
    const int nlab = (wid < 8) ? 13 : 12;   // labels wid+16j < 200

    // zero private tables + counts
    for (int i = tid; i < NWARP * 13 * 32; i += blockDim.x) s_tab[i] = make_float2(0.f, 0.f);
    for (int i = tid; i < NL; i += blockDim.x) s_cnt[i] = 0.f;
    __syncthreads();

    const int r0 = blockIdx.x * rows_per_block;
    const int r1 = min(r0 + rows_per_block, n_rows);

    for (int cb = r0; cb < r1; cb += CHUNK) {
        const int cend = min(cb + CHUNK, r1);
        if (tid < NWARP) s_qtl[tid] = 0;
        __syncthreads();

        // ---- bin: label -> (queue = label&15, payload = idx | j<<11) ----
        for (int r = cb + tid; r < cend; r += blockDim.x) {
            int l = __ldg(lab + r);
            atomicAdd(s_cnt + l, 1.f);
            int q = l & 15;
            int j = l >> 4;
            int pos = atomicAdd(s_qtl + q, 1);
            s_q[q * QCAP + pos] = (unsigned short)((r - cb) | (j << 11));
        }
        __syncthreads();

        // ---- consume: warp drains its own queue, 8 rows in flight ----
        const int n = s_qtl[wid];
        const unsigned short* q = s_q + wid * QCAP;
        float2* tab = s_tab + wid * (13 * 32) + lane;
        int k = 0;
        for (; k + 8 <= n; k += 8) {
            unsigned ev = (lane < 8) ? (unsigned)q[k + lane] : 0u;
            float2 v[8]; int jj[8];
            #pragma unroll
            for (int u = 0; u < 8; u++) {
                unsigned e = __shfl_sync(0xffffffffu, ev, u);
                jj[u] = (int)(e >> 11);
                int idx = (int)(e & 0x7FFu);
                v[u] = __ldg(lat + (size_t)(cb + idx) * 32 + lane);
            }
            #pragma unroll
            for (int u = 0; u < 8; u++) {
                float2 t = tab[jj[u] * 32];
                t.x += v[u].x; t.y += v[u].y;
                tab[jj[u] * 32] = t;
            }
        }
        for (; k < n; k++) {
            unsigned e = (unsigned)q[k];
            int j = (int)(e >> 11);
            int idx = (int)(e & 0x7FFu);
            float2 v = __ldg(lat + (size_t)(cb + idx) * 32 + lane);
            float2 t = tab[j * 32];
            t.x += v.x; t.y += v.y;
            tab[j * 32] = t;
        }
        __syncthreads();
    }

    // ---- flush: per-warp tables -> global float2 atomics; counts -> global ----
    for (int j = 0; j < nlab; j++) {
        int l = wid + 16 * j;
        float2 t = s_tab[wid * (13 * 32) + j * 32 + lane];
        atomicAdd(reinterpret_cast<float2*>(&g_sums[ds][l * NH]) + lane, t);
    }
    if (tid < NL) atomicAdd(&g_cnts[ds][tid], s_cnt[tid]);
}

// Single block: reset check, centroid update, MSE + KL -> scalar.
__global__ void finalize_kernel(const float* __restrict__ cent_p,
                                const float* __restrict__ pcnt,
                                const float* __restrict__ cent_t,
                                const float* __restrict__ tcnt,
                                const float* __restrict__ ncells,
                                float* __restrict__ out)
{
    __shared__ float red[256];
    __shared__ float s_n[2][NL];
    __shared__ float s_c[2][NL];
    __shared__ float s_new[2][NL];
    int t = threadIdx.x;

    // reset pseudo_count if max >= NCELLS_MAX (= 200 * 1000)
    red[t] = (t < NL) ? pcnt[t] : -1e30f;
    __syncthreads();
    for (int s = 128; s > 0; s >>= 1) { if (t < s) red[t] = fmaxf(red[t], red[t + s]); __syncthreads(); }
    bool reset = (red[0] >= 200000.0f);
    __syncthreads();

    if (t < NL) {
        float n0 = g_cnts[0][t];
        float c0 = reset ? 1.0f : pcnt[t];
        s_n[0][t] = n0; s_c[0][t] = c0;
        s_new[0][t] = (n0 > 5.0f) ? (c0 + n0) : c0;
        float n1 = g_cnts[1][t];
        float c1 = tcnt[t];
        s_n[1][t] = n1; s_c[1][t] = c1;
        s_new[1][t] = (n1 > 5.0f) ? (c1 + n1) : c1;
    }
    __syncthreads();

    // MSE over updated centroids. centroids layout [H, L]: i = h*200 + l.
    // g_sums standard layout: [l*64 + h].
    float acc = 0.f;
    for (int i = t; i < SUMS_SZ; i += 256) {
        int h = i / NL, l = i - h * NL;
        float cp = cent_p[i];
        float n0 = s_n[0][l];
        if (n0 > 5.0f) { float c0 = s_c[0][l]; cp = (cp * c0 + g_sums[0][l * NH + h]) / (c0 + n0); }
        float ct = cent_t[i];
        float n1 = s_n[1][l];
        if (n1 > 5.0f) { float c1 = s_c[1][l]; ct = (ct * c1 + g_sums[1][l * NH + h]) / (c1 + n1); }
        float d = cp - ct;
        acc += d * d;
    }

    // S = sum of updated pseudo counts
    red[t] = (t < NL) ? s_new[0][t] : 0.f;
    __syncthreads();
    for (int s = 128; s > 0; s >>= 1) { if (t < s) red[t] += red[t + s]; __syncthreads(); }
    float S = red[0];
    __syncthreads();

    float kl = 0.f;
    if (t < NL) {
        float p = s_new[0][t] / S;
        kl = p * (logf(p) - logf(ncells[t]));
    }

    red[t] = acc;
    __syncthreads();
    for (int s = 128; s > 0; s >>= 1) { if (t < s) red[t] += red[t + s]; __syncthreads(); }
    float mse_sum = red[0];
    __syncthreads();
    red[t] = kl;
    __syncthreads();
    for (int s = 128; s > 0; s >>= 1) { if (t < s) red[t] += red[t + s]; __syncthreads(); }
    if (t == 0) out[0] = mse_sum / (float)SUMS_SZ + red[0] / (float)NL;
}

extern "C" void kernel_launch(void* const* d_in, const int* in_sizes, int n_in,
                              void* d_out, int out_size)
{
    const float* p_lat  = (const float*)d_in[0];
    const int*   p_lab  = (const int*)  d_in[1];
    const float* t_lat  = (const float*)d_in[2];
    const int*   t_lab  = (const int*)  d_in[3];
    const float* cent_p = (const float*)d_in[4];
    const float* p_cnt  = (const float*)d_in[5];
    const float* cent_t = (const float*)d_in[6];
    const float* t_cnt  = (const float*)d_in[7];
    const float* ncells = (const float*)d_in[8];
    int n_rows = in_sizes[1];  // 1,000,000

    const int smem_bytes = 53248 + 8192 + 800 + 64;  // tables + queues + cnt + qtail
    cudaFuncSetAttribute(accum_kernel, cudaFuncAttributeMaxDynamicSharedMemorySize, smem_bytes);

    zero_kernel<<<(SUMS_SZ + 255) / 256, 256>>>();

    const int nblk = 148;  // one block per SM per dataset
    int rpb = (n_rows + nblk - 1) / nblk;
    dim3 grid(nblk, 2);
    accum_kernel<<<grid, 512, smem_bytes>>>((const float2*)p_lat, p_lab,
                                            (const float2*)t_lat, t_lab, n_rows, rpb);

    finalize_kernel<<<1, 256>>>(cent_p, p_cnt, cent_t, t_cnt, ncells, (float*)d_out);
}